// round 1
// baseline (speedup 1.0000x reference)
#include <cuda_runtime.h>
#include <cuda_bf16.h>

// STFT: B=16, T=262144, n_fft=2048, hop=512, center reflect pad 1024.
// n_frames = 513, n_bins = 1025.
// Output: [real(16,1025,513) ; imag(16,1025,513)] concatenated, fp32.

#define NFFT      2048
#define NC        1024      // packed complex FFT size
#define HOP       512
#define PADC      1024
#define T_LEN     262144
#define NFRAMES   513
#define NBINS     1025
#define NB        16
#define THREADS   512
#define PI_F      3.14159265358979323846f

__global__ __launch_bounds__(THREADS)
void stft_kernel(const float* __restrict__ x,
                 const float* __restrict__ win,
                 float* __restrict__ out) {
    __shared__ float2 bufA[NC];
    __shared__ float2 bufB[NC];

    const int f = blockIdx.x % NFRAMES;
    const int b = blockIdx.x / NFRAMES;
    const float* __restrict__ xb = x + (long)b * T_LEN;
    const int tid = threadIdx.x;

    // ---- load 2048 samples with reflect padding, window, pack to complex ----
    const int base = f * HOP - PADC;   // start in original (unpadded) coords
#pragma unroll
    for (int i = 0; i < 2; i++) {
        const int n  = tid + i * THREADS;   // complex index 0..1023
        const int j0 = 2 * n;
        const int j1 = 2 * n + 1;
        int t0 = base + j0;
        int t1 = base + j1;
        if (t0 < 0) t0 = -t0; else if (t0 >= T_LEN) t0 = 2 * T_LEN - 2 - t0;
        if (t1 < 0) t1 = -t1; else if (t1 >= T_LEN) t1 = 2 * T_LEN - 2 - t1;
        const float a = xb[t0] * win[j0];
        const float c = xb[t1] * win[j1];
        bufA[n] = make_float2(a, c);
    }
    __syncthreads();

    // ---- 1024-pt complex FFT, Stockham radix-2, 10 stages (self-sorting) ----
    float2* src = bufA;
    float2* dst = bufB;
    int n  = NC;   // current transform size
    int s  = 1;    // stride
    int ls = 0;    // log2(s)
    while (n > 1) {
        const int half = n >> 1;
        const int p = tid >> ls;          // 0..half-1
        const int q = tid & (s - 1);      // 0..s-1
        float ws, wc;
        sincosf(-2.0f * PI_F * (float)p / (float)n, &ws, &wc);
        const float2 a  = src[q + s * p];
        const float2 bb = src[q + s * (p + half)];
        const float2 sum = make_float2(a.x + bb.x, a.y + bb.y);
        const float2 dif = make_float2(a.x - bb.x, a.y - bb.y);
        const float2 dw  = make_float2(dif.x * wc - dif.y * ws,
                                       dif.x * ws + dif.y * wc);
        dst[q + s * (2 * p)]     = sum;
        dst[q + s * (2 * p + 1)] = dw;
        __syncthreads();
        float2* tmp = src; src = dst; dst = tmp;
        n = half; s <<= 1; ls++;
    }
    // 10 iterations -> result back in bufA (== src)
    const float2* __restrict__ Z = src;

    // ---- unpack real FFT: X[k], k = 0..1024 ----
    const long ro_base   = ((long)b * NBINS) * NFRAMES + f;
    const long imag_off  = (long)NB * NBINS * NFRAMES;
    for (int k = tid; k <= NC; k += THREADS) {
        const float2 zk = Z[k & (NC - 1)];          // Z[1024] -> Z[0]
        const float2 zn = Z[(NC - k) & (NC - 1)];
        // Xe = 0.5*(Z[k] + conj(Z[N-k])) ; Xo = -0.5i*(Z[k] - conj(Z[N-k]))
        const float er  = 0.5f * (zk.x + zn.x);
        const float ei  = 0.5f * (zk.y - zn.y);
        const float orr = 0.5f * (zk.y + zn.y);
        const float oi  = -0.5f * (zk.x - zn.x);
        float swk, cwk;
        sincosf(PI_F * (float)k / (float)NC, &swk, &cwk);
        // X = Xe + e^{-i*pi*k/N} * Xo
        const float xr = er + orr * cwk + oi * swk;
        const float xi = ei - orr * swk + oi * cwk;
        const long o = ro_base + (long)k * NFRAMES;
        out[o]            = xr;
        out[imag_off + o] = xi;
    }
}

extern "C" void kernel_launch(void* const* d_in, const int* in_sizes, int n_in,
                              void* d_out, int out_size) {
    const float* x   = (const float*)d_in[0];
    const float* win = (const float*)d_in[1];
    float* out = (float*)d_out;
    dim3 grid(NB * NFRAMES);
    stft_kernel<<<grid, THREADS>>>(x, win, out);
}

// round 2
// speedup vs baseline: 1.6855x; 1.6855x over previous
#include <cuda_runtime.h>
#include <cuda_bf16.h>

// STFT: B=16, T=262144, n_fft=2048, hop=512, center reflect pad 1024.
// n_frames = 513, n_bins = 1025.
// Output: [real(16,1025,513) ; imag(16,1025,513)] concatenated, fp32.
//
// Strategy: pack 2048 real -> 1024 complex, radix-4 Stockham FFT (5 stages,
// in-place two-phase), 4 frames per CTA for coalesced transposed stores.

#define NFFT      2048
#define NC        1024      // packed complex FFT size
#define HOP       512
#define PADC      1024
#define T_LEN     262144
#define NFRAMES   513
#define NBINS     1025
#define NB        16
#define THREADS   512
#define FPB       4         // frames per block
#define NGRP      129       // ceil(513/4)
#define PI_F      3.14159265358979323846f

__device__ __forceinline__ float2 cmul(float2 a, float c, float s) {
    return make_float2(a.x * c - a.y * s, a.x * s + a.y * c);
}

__global__ __launch_bounds__(THREADS, 3)
void stft_kernel(const float* __restrict__ x,
                 const float* __restrict__ win,
                 float* __restrict__ out) {
    __shared__ float2 buf[FPB][NC];   // 32 KB

    const int g   = blockIdx.x % NGRP;
    const int b   = blockIdx.x / NGRP;
    const int tid = threadIdx.x;
    const int fl  = tid >> 7;         // frame slot 0..3
    const int u   = tid & 127;        // lane within frame group
    const int f   = g * FPB + fl;     // global frame (may be >= 513, store-masked)
    const float* __restrict__ xb = x + (long)b * T_LEN;
    const int base = f * HOP - PADC;

    // ---- load 2048 samples (reflect pad at edges), window, pack to complex ----
    const bool interior = (base >= 0) && (base + NFFT <= T_LEN);
    if (interior) {
        const float2* __restrict__ xv = (const float2*)(xb + base);
        const float2* __restrict__ wv = (const float2*)win;
#pragma unroll
        for (int i = 0; i < 8; i++) {
            const int n = u + (i << 7);
            const float2 v = xv[n];
            const float2 w = wv[n];
            buf[fl][n] = make_float2(v.x * w.x, v.y * w.y);
        }
    } else {
#pragma unroll
        for (int i = 0; i < 8; i++) {
            const int n  = u + (i << 7);
            const int j0 = 2 * n;
            const int j1 = 2 * n + 1;
            int t0 = base + j0;
            int t1 = base + j1;
            t0 = (t0 < 0) ? -t0 : ((t0 >= T_LEN) ? 2 * T_LEN - 2 - t0 : t0);
            t1 = (t1 < 0) ? -t1 : ((t1 >= T_LEN) ? 2 * T_LEN - 2 - t1 : t1);
            buf[fl][n] = make_float2(xb[t0] * win[j0], xb[t1] * win[j1]);
        }
    }
    __syncthreads();

    // ---- 1024-pt complex FFT: radix-4 Stockham DIF, 5 stages, in-place ----
    // Butterfly t (0..255): reads buf[t + 256r], writes buf[t + s*(3p + r)],
    // p = t >> log2(s), twiddle w = exp(-2*pi*i*p/n), outputs scaled by w^r.
    int nsz = NC;
    int s   = 1;
    int ls  = 0;
#pragma unroll
    for (int st = 0; st < 5; st++) {
        float2 A[2][4];
#pragma unroll
        for (int h = 0; h < 2; h++) {
            const int t = u + (h << 7);
            A[h][0] = buf[fl][t];
            A[h][1] = buf[fl][t + 256];
            A[h][2] = buf[fl][t + 512];
            A[h][3] = buf[fl][t + 768];
        }
        __syncthreads();
#pragma unroll
        for (int h = 0; h < 2; h++) {
            const int t = u + (h << 7);
            const int p = t >> ls;
            const float2 a0 = A[h][0], a1 = A[h][1], a2 = A[h][2], a3 = A[h][3];
            const float t0r = a0.x + a2.x, t0i = a0.y + a2.y;
            const float t1r = a0.x - a2.x, t1i = a0.y - a2.y;
            const float t2r = a1.x + a3.x, t2i = a1.y + a3.y;
            const float t3r = a1.x - a3.x, t3i = a1.y - a3.y;
            const float2 b0 = make_float2(t0r + t2r, t0i + t2i);
            const float2 b2 = make_float2(t0r - t2r, t0i - t2i);
            const float2 b1 = make_float2(t1r + t3i, t1i - t3r);  // t1 - i*t3
            const float2 b3 = make_float2(t1r - t3i, t1i + t3r);  // t1 + i*t3
            float s1, c1;
            __sincosf((float)p * (-2.0f * PI_F / (float)nsz), &s1, &c1);
            const float c2 = c1 * c1 - s1 * s1;
            const float s2 = 2.0f * c1 * s1;
            const float c3 = c1 * c2 - s1 * s2;
            const float s3 = c1 * s2 + s1 * c2;
            const int dbase = t + s * 3 * p;
            buf[fl][dbase]         = b0;
            buf[fl][dbase + s]     = cmul(b1, c1, s1);
            buf[fl][dbase + 2 * s] = cmul(b2, c2, s2);
            buf[fl][dbase + 3 * s] = cmul(b3, c3, s3);
        }
        __syncthreads();
        nsz >>= 2;
        s   <<= 2;
        ls  += 2;
    }

    // ---- unpack real FFT bins k=0..1024, store transposed & coalesced ----
    // Thread j: frame slot = j&3, bins k = (j>>2) + 128*i. 4 consecutive
    // lanes write 4 consecutive f values -> 16B contiguous chunks.
    const int  fl2    = tid & 3;
    const int  kb     = tid >> 2;
    const int  fstore = g * FPB + fl2;
    const bool valid  = (fstore < NFRAMES);
    const long ro       = ((long)b * NBINS) * NFRAMES + fstore;
    const long imag_off = (long)NB * NBINS * NFRAMES;
    const float2* __restrict__ Z = buf[fl2];
#pragma unroll
    for (int i = 0; i < 9; i++) {
        const int k = kb + (i << 7);
        if (k <= NC) {
            const float2 zk = Z[k & (NC - 1)];
            const float2 zn = Z[(NC - k) & (NC - 1)];
            const float er  = 0.5f * (zk.x + zn.x);
            const float ei  = 0.5f * (zk.y - zn.y);
            const float orr = 0.5f * (zk.y + zn.y);
            const float oi  = -0.5f * (zk.x - zn.x);
            float swk, cwk;
            __sincosf(PI_F * (float)k * (1.0f / (float)NC), &swk, &cwk);
            const float xr = er + orr * cwk + oi * swk;
            const float xi = ei - orr * swk + oi * cwk;
            if (valid) {
                const long o = ro + (long)k * NFRAMES;
                out[o]            = xr;
                out[imag_off + o] = xi;
            }
        }
    }
}

extern "C" void kernel_launch(void* const* d_in, const int* in_sizes, int n_in,
                              void* d_out, int out_size) {
    const float* x   = (const float*)d_in[0];
    const float* win = (const float*)d_in[1];
    float* out = (float*)d_out;
    dim3 grid(NB * NGRP);
    stft_kernel<<<grid, THREADS>>>(x, win, out);
}

// round 3
// speedup vs baseline: 2.2371x; 1.3272x over previous
#include <cuda_runtime.h>
#include <cuda_bf16.h>

// STFT: B=16, T=262144, n_fft=2048, hop=512, center reflect pad 1024.
// n_frames = 513, n_bins = 1025.
// Output: [real(16,1025,513) ; imag(16,1025,513)] concatenated, fp32.
//
// radix-4 Stockham (5 stages, in-place two-phase), 4 frames/CTA,
// XOR bank swizzle + padded row stride for conflict-free smem,
// per-frame named barriers.

#define NFFT      2048
#define NC        1024      // packed complex FFT size
#define ROWS      (NC + 4)  // row stride: +4 float2 -> frames offset 4 bank-pairs
#define HOP       512
#define PADC      1024
#define T_LEN     262144
#define NFRAMES   513
#define NBINS     1025
#define NB        16
#define THREADS   512
#define FPB       4         // frames per block
#define NGRP      129       // ceil(513/4)
#define PI_F      3.14159265358979323846f

// bank swizzle: permute within each 16-element block using bits [5:4]
#define SW(i) ((i) ^ (((((unsigned)(i)) >> 4) & 3u) * 5u))

__device__ __forceinline__ float2 cmul(float2 a, float c, float s) {
    return make_float2(a.x * c - a.y * s, a.x * s + a.y * c);
}

__device__ __forceinline__ void bar_frame(int fl) {
    asm volatile("bar.sync %0, 128;" :: "r"(fl + 1) : "memory");
}

__global__ __launch_bounds__(THREADS, 3)
void stft_kernel(const float* __restrict__ x,
                 const float* __restrict__ win,
                 float* __restrict__ out) {
    __shared__ float2 buf[FPB][ROWS];   // ~32.9 KB

    const int g   = blockIdx.x % NGRP;
    const int b   = blockIdx.x / NGRP;
    const int tid = threadIdx.x;
    const int fl  = tid >> 7;         // frame slot 0..3
    const int u   = tid & 127;        // lane within frame group
    const int f   = g * FPB + fl;     // global frame (may be >= 513, store-masked)
    const float* __restrict__ xb = x + (long)b * T_LEN;
    const int base = f * HOP - PADC;

    // ---- load 2048 samples (reflect pad at edges), window, pack to complex ----
    const bool interior = (base >= 0) && (base + NFFT <= T_LEN);
    if (interior) {
        const float2* __restrict__ xv = (const float2*)(xb + base);
        const float2* __restrict__ wv = (const float2*)win;
#pragma unroll
        for (int i = 0; i < 8; i++) {
            const int n = u + (i << 7);
            const float2 v = xv[n];
            const float2 w = wv[n];
            buf[fl][SW(n)] = make_float2(v.x * w.x, v.y * w.y);
        }
    } else {
#pragma unroll
        for (int i = 0; i < 8; i++) {
            const int n  = u + (i << 7);
            const int j0 = 2 * n;
            const int j1 = 2 * n + 1;
            int t0 = base + j0;
            int t1 = base + j1;
            t0 = (t0 < 0) ? -t0 : ((t0 >= T_LEN) ? 2 * T_LEN - 2 - t0 : t0);
            t1 = (t1 < 0) ? -t1 : ((t1 >= T_LEN) ? 2 * T_LEN - 2 - t1 : t1);
            buf[fl][SW(n)] = make_float2(xb[t0] * win[j0], xb[t1] * win[j1]);
        }
    }
    bar_frame(fl);

    // ---- 1024-pt complex FFT: radix-4 Stockham DIF, 5 stages, in-place ----
    int nsz = NC;
    int s   = 1;
    int ls  = 0;
#pragma unroll
    for (int st = 0; st < 5; st++) {
        float2 A[2][4];
#pragma unroll
        for (int h = 0; h < 2; h++) {
            const int t = u + (h << 7);
            A[h][0] = buf[fl][SW(t)];
            A[h][1] = buf[fl][SW(t + 256)];
            A[h][2] = buf[fl][SW(t + 512)];
            A[h][3] = buf[fl][SW(t + 768)];
        }
        bar_frame(fl);
#pragma unroll
        for (int h = 0; h < 2; h++) {
            const int t = u + (h << 7);
            const int p = t >> ls;
            const float2 a0 = A[h][0], a1 = A[h][1], a2 = A[h][2], a3 = A[h][3];
            const float t0r = a0.x + a2.x, t0i = a0.y + a2.y;
            const float t1r = a0.x - a2.x, t1i = a0.y - a2.y;
            const float t2r = a1.x + a3.x, t2i = a1.y + a3.y;
            const float t3r = a1.x - a3.x, t3i = a1.y - a3.y;
            const float2 b0 = make_float2(t0r + t2r, t0i + t2i);
            const float2 b2 = make_float2(t0r - t2r, t0i - t2i);
            const float2 b1 = make_float2(t1r + t3i, t1i - t3r);  // t1 - i*t3
            const float2 b3 = make_float2(t1r - t3i, t1i + t3r);  // t1 + i*t3
            float s1, c1;
            __sincosf((float)p * (-2.0f * PI_F / (float)nsz), &s1, &c1);
            const float c2 = c1 * c1 - s1 * s1;
            const float s2 = 2.0f * c1 * s1;
            const float c3 = c1 * c2 - s1 * s2;
            const float s3 = c1 * s2 + s1 * c2;
            const int dbase = t + s * 3 * p;
            buf[fl][SW(dbase)]         = b0;
            buf[fl][SW(dbase + s)]     = cmul(b1, c1, s1);
            buf[fl][SW(dbase + 2 * s)] = cmul(b2, c2, s2);
            buf[fl][SW(dbase + 3 * s)] = cmul(b3, c3, s3);
        }
        bar_frame(fl);
        nsz >>= 2;
        s   <<= 2;
        ls  += 2;
    }

    // all 4 frames must be complete before cross-frame unpack/store
    __syncthreads();

    // ---- unpack real FFT bins k=0..1024, store transposed & coalesced ----
    // Thread j: frame slot = j&3, bins k = (j>>2) + 128*i. 4 consecutive
    // lanes write 4 consecutive f values -> 16B contiguous chunks.
    const int  fl2    = tid & 3;
    const int  kb     = tid >> 2;
    const int  fstore = g * FPB + fl2;
    const bool valid  = (fstore < NFRAMES);
    const long ro       = ((long)b * NBINS) * NFRAMES + fstore;
    const long imag_off = (long)NB * NBINS * NFRAMES;
    const float2* __restrict__ Z = buf[fl2];
#pragma unroll
    for (int i = 0; i < 9; i++) {
        const int k = kb + (i << 7);
        if (k <= NC) {
            const float2 zk = Z[SW(k & (NC - 1))];
            const float2 zn = Z[SW((NC - k) & (NC - 1))];
            const float er  = 0.5f * (zk.x + zn.x);
            const float ei  = 0.5f * (zk.y - zn.y);
            const float orr = 0.5f * (zk.y + zn.y);
            const float oi  = -0.5f * (zk.x - zn.x);
            float swk, cwk;
            __sincosf(PI_F * (float)k * (1.0f / (float)NC), &swk, &cwk);
            const float xr = er + orr * cwk + oi * swk;
            const float xi = ei - orr * swk + oi * cwk;
            if (valid) {
                const long o = ro + (long)k * NFRAMES;
                out[o]            = xr;
                out[imag_off + o] = xi;
            }
        }
    }
}

extern "C" void kernel_launch(void* const* d_in, const int* in_sizes, int n_in,
                              void* d_out, int out_size) {
    const float* x   = (const float*)d_in[0];
    const float* win = (const float*)d_in[1];
    float* out = (float*)d_out;
    dim3 grid(NB * NGRP);
    stft_kernel<<<grid, THREADS>>>(x, win, out);
}

// round 4
// speedup vs baseline: 2.3869x; 1.0670x over previous
#include <cuda_runtime.h>
#include <cuda_bf16.h>

// STFT: B=16, T=262144, n_fft=2048, hop=512, center reflect pad 1024.
// n_frames = 513, n_bins = 1025. Output [real(16,1025,513); imag(...)] fp32.
//
// 1024-pt complex FFT per frame (real packing), Stockham radices 8,8,4,4.
// Stage 1 reads gmem directly; last stage fused with rfft unpack in registers.
// Bank bijection P(L)=L^((L>>3)&15); 4 frames/CTA; per-frame named barriers.

#define NC        1024
#define ROWSTRIDE 1028      // == 4 (mod 16): frame rows offset 4 bank-pairs
#define HOP       512
#define PADC      1024
#define T_LEN     262144
#define NFFT      2048
#define NFRAMES   513
#define NBINS     1025
#define NB        16
#define THREADS   512
#define FPB       4
#define NGRP      129
#define PI_F      3.14159265358979323846f
#define C4        0.70710678118654752f

#define PHY(i) ((i) ^ ((((unsigned)(i)) >> 3) & 15u))

__device__ __forceinline__ float2 cadd(float2 a, float2 b) { return make_float2(a.x + b.x, a.y + b.y); }
__device__ __forceinline__ float2 csub(float2 a, float2 b) { return make_float2(a.x - b.x, a.y - b.y); }
__device__ __forceinline__ float2 cmulc(float2 a, float2 w) {
    return make_float2(a.x * w.x - a.y * w.y, a.x * w.y + a.y * w.x);
}

// 8-point DFT, natural-order outputs (DIF building block)
__device__ __forceinline__ void fft8(float2* a) {
    float2 e0 = cadd(a[0], a[4]), e1 = cadd(a[1], a[5]);
    float2 e2 = cadd(a[2], a[6]), e3 = cadd(a[3], a[7]);
    float2 o0 = csub(a[0], a[4]), o1 = csub(a[1], a[5]);
    float2 o2 = csub(a[2], a[6]), o3 = csub(a[3], a[7]);
    float2 ee0 = cadd(e0, e2), ee1 = cadd(e1, e3);
    float2 eo0 = csub(e0, e2), eo1 = csub(e1, e3);
    a[0] = cadd(ee0, ee1);
    a[4] = csub(ee0, ee1);
    a[2] = make_float2(eo0.x + eo1.y, eo0.y - eo1.x);   // eo0 - i*eo1
    a[6] = make_float2(eo0.x - eo1.y, eo0.y + eo1.x);   // eo0 + i*eo1
    float2 p1 = make_float2(C4 * (o1.x + o1.y), C4 * (o1.y - o1.x));    // o1*W8
    float2 p2 = make_float2(o2.y, -o2.x);                               // o2*(-i)
    float2 p3 = make_float2(C4 * (o3.y - o3.x), -C4 * (o3.x + o3.y));   // o3*W8^3
    float2 s0 = cadd(o0, p2), s1 = cadd(p1, p3);
    float2 d0 = csub(o0, p2), d1 = csub(p1, p3);
    a[1] = cadd(s0, s1);
    a[5] = csub(s0, s1);
    a[3] = make_float2(d0.x + d1.y, d0.y - d1.x);
    a[7] = make_float2(d0.x - d1.y, d0.y + d1.x);
}

// 4-point DFT (DIF building block): outputs b0,b1,b2,b3 in r-order
__device__ __forceinline__ void fft4(float2& a0, float2& a1, float2& a2, float2& a3) {
    float2 t0 = cadd(a0, a2), t1 = csub(a0, a2);
    float2 t2 = cadd(a1, a3), t3 = csub(a1, a3);
    a0 = cadd(t0, t2);
    a2 = csub(t0, t2);
    float2 b1 = make_float2(t1.x + t3.y, t1.y - t3.x);  // t1 - i*t3
    float2 b3 = make_float2(t1.x - t3.y, t1.y + t3.x);  // t1 + i*t3
    a1 = b1;
    a3 = b3;
}

__device__ __forceinline__ void bar_frame(int fl) {
    asm volatile("bar.sync %0, 128;" :: "r"(fl + 1) : "memory");
}

// rfft unpack for a conjugate pair (k, NC-k): inputs zk=Z[k], zn=Z[NC-k],
// (cw,sw) = (cos,sin)(pi*k/NC). Outputs X[k], X[NC-k].
__device__ __forceinline__ void unpack_pair(float2 zk, float2 zn, float cw, float sw,
                                            float2& Xk, float2& Xc) {
    const float er  = 0.5f * (zk.x + zn.x);
    const float ei  = 0.5f * (zk.y - zn.y);
    const float orr = 0.5f * (zk.y + zn.y);
    const float oi  = 0.5f * (zn.x - zk.x);
    const float pr  = orr * cw + oi * sw;
    const float pi2 = orr * sw - oi * cw;
    Xk = make_float2(er + pr,  ei - pi2);
    Xc = make_float2(er - pr, -ei - pi2);
}

__global__ __launch_bounds__(THREADS, 2)
void stft_kernel(const float* __restrict__ x,
                 const float* __restrict__ win,
                 float* __restrict__ out) {
    __shared__ float2 buf[FPB][ROWSTRIDE];   // ~32.9 KB

    const int g   = blockIdx.x % NGRP;
    const int b   = blockIdx.x / NGRP;
    const int tid = threadIdx.x;
    const int fl  = tid >> 7;          // frame slot 0..3
    const int u   = tid & 127;         // lane within frame
    const int f   = g * FPB + fl;      // global frame (phantom if >= 513)
    const float* __restrict__ xb = x + (long)b * T_LEN;
    const int base = f * HOP - PADC;

    float2 a[8];

    // ---- stage 1: radix-8, n=1024, s=1 — read gmem directly ----
    // element n = u + 128*r  <-  (x[2n]*w[2n], x[2n+1]*w[2n+1])
    const bool interior = (base >= 0) && (base + NFFT <= T_LEN);
    if (interior) {
        const float2* __restrict__ xv = (const float2*)(xb + base);
        const float2* __restrict__ wv = (const float2*)win;
#pragma unroll
        for (int r = 0; r < 8; r++) {
            const int n = u + (r << 7);
            const float2 v = xv[n];
            const float2 w = wv[n];
            a[r] = make_float2(v.x * w.x, v.y * w.y);
        }
    } else {
#pragma unroll
        for (int r = 0; r < 8; r++) {
            const int n = u + (r << 7);
            int t0 = base + 2 * n;
            int t1 = base + 2 * n + 1;
            t0 = (t0 < 0) ? -t0 : ((t0 >= T_LEN) ? 2 * T_LEN - 2 - t0 : t0);
            t1 = (t1 < 0) ? -t1 : ((t1 >= T_LEN) ? 2 * T_LEN - 2 - t1 : t1);
            a[r] = make_float2(xb[t0] * win[2 * n], xb[t1] * win[2 * n + 1]);
        }
    }
    fft8(a);
    {   // twiddle w = W1024^u, apply w^r; write dst[8u + r]
        float s1, c1;
        __sincosf((float)u * (-2.0f * PI_F / 1024.0f), &s1, &c1);
        const float2 w1 = make_float2(c1, s1);
        float2 wk = w1;
        a[1] = cmulc(a[1], wk);
#pragma unroll
        for (int r = 2; r < 8; r++) { wk = cmulc(wk, w1); a[r] = cmulc(a[r], wk); }
#pragma unroll
        for (int r = 0; r < 8; r++) buf[fl][PHY(8 * u + r)] = a[r];
    }
    bar_frame(fl);

    // ---- stage 2: radix-8, n=128, s=8 ----
#pragma unroll
    for (int r = 0; r < 8; r++) a[r] = buf[fl][PHY(u + (r << 7))];
    bar_frame(fl);
    fft8(a);
    {
        const int p = u >> 3;
        float s1, c1;
        __sincosf((float)p * (-2.0f * PI_F / 128.0f), &s1, &c1);
        const float2 w1 = make_float2(c1, s1);
        float2 wk = w1;
        a[1] = cmulc(a[1], wk);
#pragma unroll
        for (int r = 2; r < 8; r++) { wk = cmulc(wk, w1); a[r] = cmulc(a[r], wk); }
        const int dbase = u + 56 * p;   // t + s*(R-1)*p, s=8
#pragma unroll
        for (int r = 0; r < 8; r++) buf[fl][PHY(dbase + 8 * r)] = a[r];
    }
    bar_frame(fl);

    // ---- stage 3: radix-4 x2, n=16, s=64 ----
    {
        float2 A4[2][4];
#pragma unroll
        for (int h = 0; h < 2; h++) {
            const int t = u + (h << 7);
#pragma unroll
            for (int r = 0; r < 4; r++) A4[h][r] = buf[fl][PHY(t + (r << 8))];
        }
        bar_frame(fl);
#pragma unroll
        for (int h = 0; h < 2; h++) {
            const int t = u + (h << 7);
            const int p = t >> 6;
            fft4(A4[h][0], A4[h][1], A4[h][2], A4[h][3]);
            float s1, c1;
            __sincosf((float)p * (-2.0f * PI_F / 16.0f), &s1, &c1);
            const float c2 = c1 * c1 - s1 * s1;
            const float s2 = 2.0f * c1 * s1;
            const float c3 = c1 * c2 - s1 * s2;
            const float s3 = c1 * s2 + s1 * c2;
            const int dbase = t + 192 * p;
            buf[fl][PHY(dbase)]       = A4[h][0];
            buf[fl][PHY(dbase + 64)]  = cmulc(A4[h][1], make_float2(c1, s1));
            buf[fl][PHY(dbase + 128)] = cmulc(A4[h][2], make_float2(c2, s2));
            buf[fl][PHY(dbase + 192)] = cmulc(A4[h][3], make_float2(c3, s3));
        }
        bar_frame(fl);
    }

    // ---- stage 4 (radix-4, trivial twiddles) fused with rfft unpack ----
    {
        const int t1 = u;
        const int t2 = (u == 0) ? 128 : 256 - u;
        float2 z1[4], z2[4];
#pragma unroll
        for (int r = 0; r < 4; r++) {
            z1[r] = buf[fl][PHY(t1 + (r << 8))];
            z2[r] = buf[fl][PHY(t2 + (r << 8))];
        }
        bar_frame(fl);
        fft4(z1[0], z1[1], z1[2], z1[3]);   // Z[t1 + 256r] = z1[r]
        fft4(z2[0], z2[1], z2[2], z2[3]);   // Z[t2 + 256r] = z2[r]

        if (u == 0) {
            // bins 0,1024,512 and pairs (256,768),(128,896),(384,640)
            buf[fl][0]    = make_float2(z1[0].x + z1[0].y, 0.0f);
            buf[fl][1024] = make_float2(z1[0].x - z1[0].y, 0.0f);
            buf[fl][512]  = make_float2(z1[2].x, -z1[2].y);
            float2 Xk, Xc;
            unpack_pair(z1[1], z1[3], C4, C4, Xk, Xc);            // k=256
            buf[fl][256] = Xk; buf[fl][768] = Xc;
            unpack_pair(z2[0], z2[3], 0.92387953f, 0.38268343f, Xk, Xc);  // k=128
            buf[fl][128] = Xk; buf[fl][896] = Xc;
            unpack_pair(z2[1], z2[2], 0.38268343f, 0.92387953f, Xk, Xc);  // k=384
            buf[fl][384] = Xk; buf[fl][640] = Xc;
        } else {
            float ca, sa;
            __sincosf((float)u * (PI_F / 1024.0f), &sa, &ca);
            const float cp = C4 * (ca - sa);   // cos(pi/4 + a)
            const float sp = C4 * (ca + sa);   // sin(pi/4 + a)
            float2 Xk, Xc;
            // k=u <-> 1024-u
            unpack_pair(z1[0], z2[3], ca, sa, Xk, Xc);
            buf[fl][u] = Xk; buf[fl][1024 - u] = Xc;
            // k=u+256 <-> 768-u : theta = pi/4 + a
            unpack_pair(z1[1], z2[2], cp, sp, Xk, Xc);
            buf[fl][u + 256] = Xk; buf[fl][768 - u] = Xc;
            // k=u+512 <-> 512-u : theta = pi/2 + a -> (-sa, ca)
            unpack_pair(z1[2], z2[1], -sa, ca, Xk, Xc);
            buf[fl][u + 512] = Xk; buf[fl][512 - u] = Xc;
            // k=u+768 <-> 256-u : theta = 3pi/4 + a -> (-sp, cp)
            unpack_pair(z1[3], z2[0], -sp, cp, Xk, Xc);
            buf[fl][u + 768] = Xk; buf[fl][256 - u] = Xc;
        }
    }
    __syncthreads();

    // ---- coalesced transposed store: lane j -> frame j&3, bin (tid>>2)+128i ----
    const int  fl2    = tid & 3;
    const int  kb     = tid >> 2;
    const int  fstore = g * FPB + fl2;
    const bool valid  = (fstore < NFRAMES);
    const long ro       = ((long)b * NBINS) * NFRAMES + fstore;
    const long imag_off = (long)NB * NBINS * NFRAMES;
    const float2* __restrict__ Xrow = buf[fl2];
#pragma unroll
    for (int i = 0; i < 9; i++) {
        const int k = kb + (i << 7);
        if (k <= NC && valid) {
            const float2 X = Xrow[k];
            const long o = ro + (long)k * NFRAMES;
            out[o]            = X.x;
            out[imag_off + o] = X.y;
        }
    }
}

extern "C" void kernel_launch(void* const* d_in, const int* in_sizes, int n_in,
                              void* d_out, int out_size) {
    const float* x   = (const float*)d_in[0];
    const float* win = (const float*)d_in[1];
    float* out = (float*)d_out;
    dim3 grid(NB * NGRP);
    stft_kernel<<<grid, THREADS>>>(x, win, out);
}